// round 4
// baseline (speedup 1.0000x reference)
#include <cuda_runtime.h>
#include <math.h>

#define BB 2
#define TT 2048
#define CC 1024
#define HH 16
#define DHD 64
#define C3 3072
#define MTOT (BB*TT)   // 4096

// Scratch (no allocation allowed): qkv [B,T,3C], attn [B,T,C]
__device__ float g_qkv[BB * TT * C3];
__device__ float g_attn[BB * TT * CC];

// ---------------------------------------------------------------------------
// Tiled fp32 SGEMM with bias: C[M,N] = A[M,K] @ W[K,N] + bias[N]
// BM=BN=128, BK=16, 256 threads, 8x8 per thread.
// ---------------------------------------------------------------------------
__global__ void __launch_bounds__(256)
sgemm_bias_kernel(const float* __restrict__ A, const float* __restrict__ W,
                  const float* __restrict__ bias, float* __restrict__ Cout,
                  int M, int N, int K) {
    __shared__ float As[16][132];   // padded: k-major, transposed A tile
    __shared__ float Bs[16][128];

    const int tid = threadIdx.x;
    const int tx = tid & 15;        // 0..15 -> n
    const int ty = tid >> 4;        // 0..15 -> m
    const int bx = blockIdx.x;      // n tile
    const int by = blockIdx.y;      // m tile

    const float* Ab = A + (size_t)by * 128 * K;
    const float* Bb = W + (size_t)bx * 128;

    float acc[8][8];
#pragma unroll
    for (int i = 0; i < 8; i++)
#pragma unroll
        for (int j = 0; j < 8; j++) acc[i][j] = 0.0f;

    for (int k0 = 0; k0 < K; k0 += 16) {
        // Load A tile: 128 rows x 16 cols = 512 float4, 2 per thread.
#pragma unroll
        for (int r = 0; r < 2; r++) {
            int id = tid + r * 256;
            int row = id >> 2;            // 0..127
            int kc  = (id & 3) * 4;       // 0,4,8,12
            float4 v = *(const float4*)(Ab + (size_t)row * K + k0 + kc);
            As[kc + 0][row] = v.x;
            As[kc + 1][row] = v.y;
            As[kc + 2][row] = v.z;
            As[kc + 3][row] = v.w;
        }
        // Load B tile: 16 rows x 128 cols = 512 float4, 2 per thread (coalesced).
#pragma unroll
        for (int r = 0; r < 2; r++) {
            int id = tid + r * 256;
            int row = id >> 5;            // 0..15
            int c4  = (id & 31) * 4;      // 0..124
            *(float4*)&Bs[row][c4] =
                *(const float4*)(Bb + (size_t)(k0 + row) * N + c4);
        }
        __syncthreads();

#pragma unroll
        for (int k = 0; k < 16; k++) {
            float a[8], b[8];
            *(float4*)&a[0] = *(const float4*)&As[k][ty * 8];
            *(float4*)&a[4] = *(const float4*)&As[k][ty * 8 + 4];
            *(float4*)&b[0] = *(const float4*)&Bs[k][tx * 8];
            *(float4*)&b[4] = *(const float4*)&Bs[k][tx * 8 + 4];
#pragma unroll
            for (int i = 0; i < 8; i++)
#pragma unroll
                for (int j = 0; j < 8; j++)
                    acc[i][j] = fmaf(a[i], b[j], acc[i][j]);
        }
        __syncthreads();
    }

    // Epilogue: bias + store
    const int m0 = by * 128 + ty * 8;
    const int n0 = bx * 128 + tx * 8;
    float bv[8];
#pragma unroll
    for (int j = 0; j < 8; j++) bv[j] = bias[n0 + j];
#pragma unroll
    for (int i = 0; i < 8; i++) {
        float* cp = Cout + (size_t)(m0 + i) * N + n0;
        float4 o0, o1;
        o0.x = acc[i][0] + bv[0]; o0.y = acc[i][1] + bv[1];
        o0.z = acc[i][2] + bv[2]; o0.w = acc[i][3] + bv[3];
        o1.x = acc[i][4] + bv[4]; o1.y = acc[i][5] + bv[5];
        o1.z = acc[i][6] + bv[6]; o1.w = acc[i][7] + bv[7];
        *(float4*)cp       = o0;
        *(float4*)(cp + 4) = o1;
    }
}

// ---------------------------------------------------------------------------
// Flash attention: grid (T/128, H, B), 128 threads, 1 thread = 1 query row.
// Q row pre-scaled by 1/sqrt(64) in registers; K/V tiles (32 x 64) in smem,
// read via broadcast LDS.128. Online softmax, fp32 accumulation.
// Writes attn output as [B,T,C] (head-interleaved) directly.
// ---------------------------------------------------------------------------
__global__ void __launch_bounds__(128)
flash_attn_kernel(const float* __restrict__ qkv, float* __restrict__ attn) {
    const int qt = blockIdx.x;
    const int h  = blockIdx.y;
    const int b  = blockIdx.z;
    const int tid = threadIdx.x;
    const int row = qt * 128 + tid;

    const float* base = qkv + (size_t)b * TT * C3;

    // Q row -> registers, pre-scaled
    float4 q[16];
    {
        const float4* qp = (const float4*)(base + (size_t)row * C3 + h * DHD);
#pragma unroll
        for (int d = 0; d < 16; d++) {
            float4 v = qp[d];
            v.x *= 0.125f; v.y *= 0.125f; v.z *= 0.125f; v.w *= 0.125f;
            q[d] = v;
        }
    }

    float4 acc[16];
#pragma unroll
    for (int d = 0; d < 16; d++) acc[d] = make_float4(0.f, 0.f, 0.f, 0.f);
    float mmax = -INFINITY;
    float lsum = 0.0f;

    __shared__ float4 Ks[32][16];
    __shared__ float4 Vs[32][16];

    for (int kt = 0; kt < TT; kt += 32) {
        __syncthreads();
        // Load K/V tiles: 32 rows x 16 float4 each; 4 float4 per thread per tile.
#pragma unroll
        for (int r = 0; r < 4; r++) {
            int id = tid + r * 128;
            int kr = id >> 4;           // 0..31
            int c4 = id & 15;           // 0..15
            const float* krow = base + (size_t)(kt + kr) * C3 + CC + h * DHD;
            const float* vrow = base + (size_t)(kt + kr) * C3 + 2 * CC + h * DHD;
            Ks[kr][c4] = ((const float4*)krow)[c4];
            Vs[kr][c4] = ((const float4*)vrow)[c4];
        }
        __syncthreads();

        // S = q . K_j  (32 independent dot chains, 4 partials each)
        float s[32];
#pragma unroll
        for (int j = 0; j < 32; j++) {
            float s0 = 0.f, s1 = 0.f, s2 = 0.f, s3 = 0.f;
#pragma unroll
            for (int d = 0; d < 16; d++) {
                float4 kv = Ks[j][d];
                s0 = fmaf(q[d].x, kv.x, s0);
                s1 = fmaf(q[d].y, kv.y, s1);
                s2 = fmaf(q[d].z, kv.z, s2);
                s3 = fmaf(q[d].w, kv.w, s3);
            }
            s[j] = (s0 + s1) + (s2 + s3);
        }

        // Online softmax update
        float mt = s[0];
#pragma unroll
        for (int j = 1; j < 32; j++) mt = fmaxf(mt, s[j]);
        float mnew = fmaxf(mmax, mt);
        float corr = __expf(mmax - mnew);   // 0 on first tile (mmax = -inf)
        lsum *= corr;
#pragma unroll
        for (int d = 0; d < 16; d++) {
            acc[d].x *= corr; acc[d].y *= corr;
            acc[d].z *= corr; acc[d].w *= corr;
        }
#pragma unroll
        for (int j = 0; j < 32; j++) {
            float p = __expf(s[j] - mnew);
            lsum += p;
#pragma unroll
            for (int d = 0; d < 16; d++) {
                float4 vv = Vs[j][d];
                acc[d].x = fmaf(p, vv.x, acc[d].x);
                acc[d].y = fmaf(p, vv.y, acc[d].y);
                acc[d].z = fmaf(p, vv.z, acc[d].z);
                acc[d].w = fmaf(p, vv.w, acc[d].w);
            }
        }
        mmax = mnew;
    }

    const float inv = 1.0f / lsum;
    float* op = attn + (size_t)(b * TT + row) * CC + h * DHD;
#pragma unroll
    for (int d = 0; d < 16; d++) {
        float4 o = acc[d];
        o.x *= inv; o.y *= inv; o.z *= inv; o.w *= inv;
        ((float4*)op)[d] = o;
    }
}

// ---------------------------------------------------------------------------
// Launch
// ---------------------------------------------------------------------------
extern "C" void kernel_launch(void* const* d_in, const int* in_sizes, int n_in,
                              void* d_out, int out_size) {
    const float* x     = (const float*)d_in[0];
    const float* Wqkv  = (const float*)d_in[1];
    const float* bqkv  = (const float*)d_in[2];
    const float* Wout  = (const float*)d_in[3];
    const float* bout  = (const float*)d_in[4];
    float* out = (float*)d_out;

    float* qkv = nullptr;
    float* attn = nullptr;
    cudaGetSymbolAddress((void**)&qkv, g_qkv);
    cudaGetSymbolAddress((void**)&attn, g_attn);

    // 1) QKV projection: [4096,1024] @ [1024,3072] + b
    {
        dim3 grid(C3 / 128, MTOT / 128);
        sgemm_bias_kernel<<<grid, 256>>>(x, Wqkv, bqkv, qkv, MTOT, C3, CC);
    }

    // 2) Fused attention (flash): qkv -> attn [B,T,C]
    {
        dim3 grid(TT / 128, HH, BB);
        flash_attn_kernel<<<grid, 128>>>(qkv, attn);
    }

    // 3) Output projection: [4096,1024] @ [1024,1024] + b
    {
        dim3 grid(CC / 128, MTOT / 128);
        sgemm_bias_kernel<<<grid, 256>>>(attn, Wout, bout, out, MTOT, CC, CC);
    }
}

// round 5
// speedup vs baseline: 1.7474x; 1.7474x over previous
#include <cuda_runtime.h>
#include <math.h>
#include <stdint.h>

#define BB 2
#define TT 2048
#define CC 1024
#define HH 16
#define C3 3072
#define MTOT (BB*TT)   // 4096

// Scratch (no allocation allowed)
__device__ float g_qkv[(size_t)MTOT * C3];
__device__ float g_attn[(size_t)MTOT * CC];

// ---------------------------------------------------------------------------
// tf32 helpers
// ---------------------------------------------------------------------------
__device__ __forceinline__ float tf32_rna(float x) {
    float r; asm("cvt.rna.tf32.f32 %0, %1;" : "=f"(r) : "f"(x)); return r;
}
__device__ __forceinline__ void split_tf32(float x, uint32_t& hi, uint32_t& lo) {
    float h = tf32_rna(x);
    float l = tf32_rna(x - h);
    hi = __float_as_uint(h);
    lo = __float_as_uint(l);
}
// D (+)= A(16x8) * B(8x8), tf32 inputs, fp32 accum. In-place C==D.
__device__ __forceinline__ void mma8(float* d,
                                     uint32_t a0, uint32_t a1, uint32_t a2, uint32_t a3,
                                     uint32_t b0, uint32_t b1) {
    asm volatile(
        "mma.sync.aligned.m16n8k8.row.col.f32.tf32.tf32.f32 "
        "{%0,%1,%2,%3}, {%4,%5,%6,%7}, {%8,%9}, {%0,%1,%2,%3};\n"
        : "+f"(d[0]), "+f"(d[1]), "+f"(d[2]), "+f"(d[3])
        : "r"(a0), "r"(a1), "r"(a2), "r"(a3), "r"(b0), "r"(b1));
}

// ---------------------------------------------------------------------------
// GEMM (tf32x3, ~fp32 accurate): C[M,N] = A[M,K] @ W[K,N] + bias[N]
// BM=BN=128, BK=32, 256 threads (8 warps, 2x4 grid, warp tile 64x32).
// ---------------------------------------------------------------------------
__global__ void __launch_bounds__(256, 2)
gemm_tf32x3(const float* __restrict__ A, const float* __restrict__ W,
            const float* __restrict__ bias, float* __restrict__ Cout,
            int M, int N, int K) {
    __shared__ float As[128][36];   // row-major A tile (stride 36 -> frag loads conflict-free)
    __shared__ float Bs[32][136];   // row-major B tile (stride 136 -> frag loads conflict-free)

    const int tid  = threadIdx.x;
    const int lane = tid & 31;
    const int wid  = tid >> 5;
    const int g = lane >> 2;        // 0..7
    const int t = lane & 3;         // 0..3
    const int wm = (wid >> 2) * 64; // 0 / 64
    const int wn = (wid & 3) * 32;  // 0..96

    const float* Ab = A + (size_t)blockIdx.y * 128 * K;
    const float* Bb = W + (size_t)blockIdx.x * 128;

    float acc[4][4][4];
#pragma unroll
    for (int i = 0; i < 4; i++)
#pragma unroll
        for (int j = 0; j < 4; j++)
#pragma unroll
            for (int r = 0; r < 4; r++) acc[i][j][r] = 0.0f;

    for (int k0 = 0; k0 < K; k0 += 32) {
        // A tile: 128x32 floats = 1024 float4, 4 per thread
#pragma unroll
        for (int r = 0; r < 4; r++) {
            int id = tid + r * 256;
            int row = id >> 3;          // 0..127
            int c4  = (id & 7) * 4;     // 0..28
            *(float4*)&As[row][c4] =
                *(const float4*)(Ab + (size_t)row * K + k0 + c4);
        }
        // B tile: 32x128 floats = 1024 float4, 4 per thread
#pragma unroll
        for (int r = 0; r < 4; r++) {
            int id = tid + r * 256;
            int row = id >> 5;          // 0..31
            int c4  = (id & 31) * 4;    // 0..124
            *(float4*)&Bs[row][c4] =
                *(const float4*)(Bb + (size_t)(k0 + row) * N + c4);
        }
        __syncthreads();

#pragma unroll
        for (int kk = 0; kk < 32; kk += 8) {
            uint32_t ah[4][4], al[4][4];
#pragma unroll
            for (int mt = 0; mt < 4; mt++) {
                int r0 = wm + mt * 16;
                split_tf32(As[r0 + g    ][kk + t    ], ah[mt][0], al[mt][0]);
                split_tf32(As[r0 + g + 8][kk + t    ], ah[mt][1], al[mt][1]);
                split_tf32(As[r0 + g    ][kk + t + 4], ah[mt][2], al[mt][2]);
                split_tf32(As[r0 + g + 8][kk + t + 4], ah[mt][3], al[mt][3]);
            }
            uint32_t bh[4][2], bl[4][2];
#pragma unroll
            for (int nt = 0; nt < 4; nt++) {
                int c0 = wn + nt * 8;
                split_tf32(Bs[kk + t    ][c0 + g], bh[nt][0], bl[nt][0]);
                split_tf32(Bs[kk + t + 4][c0 + g], bh[nt][1], bl[nt][1]);
            }
#pragma unroll
            for (int mt = 0; mt < 4; mt++)
#pragma unroll
                for (int nt = 0; nt < 4; nt++) {
                    mma8(acc[mt][nt], al[mt][0], al[mt][1], al[mt][2], al[mt][3],
                         bh[nt][0], bh[nt][1]);
                    mma8(acc[mt][nt], ah[mt][0], ah[mt][1], ah[mt][2], ah[mt][3],
                         bl[nt][0], bl[nt][1]);
                    mma8(acc[mt][nt], ah[mt][0], ah[mt][1], ah[mt][2], ah[mt][3],
                         bh[nt][0], bh[nt][1]);
                }
        }
        __syncthreads();
    }

    // Epilogue
    float bv[4][2];
#pragma unroll
    for (int nt = 0; nt < 4; nt++) {
        int col = blockIdx.x * 128 + wn + nt * 8 + 2 * t;
        bv[nt][0] = bias[col];
        bv[nt][1] = bias[col + 1];
    }
#pragma unroll
    for (int mt = 0; mt < 4; mt++) {
        int row = blockIdx.y * 128 + wm + mt * 16 + g;
#pragma unroll
        for (int nt = 0; nt < 4; nt++) {
            int col = blockIdx.x * 128 + wn + nt * 8 + 2 * t;
            float2 v0 = make_float2(acc[mt][nt][0] + bv[nt][0],
                                    acc[mt][nt][1] + bv[nt][1]);
            float2 v1 = make_float2(acc[mt][nt][2] + bv[nt][0],
                                    acc[mt][nt][3] + bv[nt][1]);
            *(float2*)&Cout[(size_t)row * N + col]       = v0;
            *(float2*)&Cout[(size_t)(row + 8) * N + col] = v1;
        }
    }
}

// ---------------------------------------------------------------------------
// Flash attention, tensor-core tf32. S=QK^T in tf32x3 (accurate scores),
// P*V in plain tf32 (P rna-rounded, consistent with l-sum).
// grid (T/64, H, B), 128 threads (4 warps, 16 q-rows per warp).
// ---------------------------------------------------------------------------
#define KS_STRIDE 68
#define VS_STRIDE 72
#define PS_STRIDE 68
#define SM_KSH 0
#define SM_KSL (64 * KS_STRIDE)                 // 4352
#define SM_VS  (SM_KSL + 64 * KS_STRIDE)        // 8704
#define SM_PS  (SM_VS + 64 * VS_STRIDE)         // 13312
#define ATTN_SMEM_FLOATS (SM_PS + 4 * 16 * PS_STRIDE)   // 17664
#define ATTN_SMEM_BYTES (ATTN_SMEM_FLOATS * 4)          // 70656

__global__ void __launch_bounds__(128)
attn_tf32(const float* __restrict__ qkv, float* __restrict__ attn) {
    extern __shared__ float sm[];
    float* Ksh = sm + SM_KSH;   // [64][68] tf32-hi of K
    float* Ksl = sm + SM_KSL;   // [64][68] tf32-lo of K
    float* Vs  = sm + SM_VS;    // [64][72] tf32(V)
    float* Ps  = sm + SM_PS;    // [4][16][68] per-warp P

    const int tid  = threadIdx.x;
    const int lane = tid & 31;
    const int wid  = tid >> 5;
    const int g = lane >> 2;
    const int t = lane & 3;
    const int qt = blockIdx.x, h = blockIdx.y, b = blockIdx.z;

    const float* base = qkv + (size_t)b * TT * C3;
    const int q0 = qt * 64 + wid * 16;

    // Q fragments (hi/lo), scaled by 1/sqrt(64), loaded once from global.
    uint32_t qh[8][4], ql[8][4];
#pragma unroll
    for (int kk = 0; kk < 8; kk++) {
        int c = kk * 8;
        const float* qr0 = base + (size_t)(q0 + g) * C3 + h * 64;
        const float* qr1 = base + (size_t)(q0 + g + 8) * C3 + h * 64;
        split_tf32(qr0[c + t    ] * 0.125f, qh[kk][0], ql[kk][0]);
        split_tf32(qr1[c + t    ] * 0.125f, qh[kk][1], ql[kk][1]);
        split_tf32(qr0[c + t + 4] * 0.125f, qh[kk][2], ql[kk][2]);
        split_tf32(qr1[c + t + 4] * 0.125f, qh[kk][3], ql[kk][3]);
    }

    float mrow0 = -INFINITY, mrow1 = -INFINITY;
    float lrow0 = 0.0f, lrow1 = 0.0f;
    float oacc[8][4];
#pragma unroll
    for (int nt = 0; nt < 8; nt++)
#pragma unroll
        for (int r = 0; r < 4; r++) oacc[nt][r] = 0.0f;

    float* Pw = Ps + wid * 16 * PS_STRIDE;

    for (int kt = 0; kt < TT; kt += 64) {
        __syncthreads();
        // Load K (split hi/lo) and V (tf32-rounded): 64 rows x 16 float4 each.
#pragma unroll
        for (int r = 0; r < 8; r++) {
            int id = tid + r * 128;
            int row = id >> 4;          // 0..63
            int c4  = (id & 15) * 4;    // 0..60
            const float* kp = base + (size_t)(kt + row) * C3 + CC + h * 64 + c4;
            float4 kv = *(const float4*)kp;
            float4 vv = *(const float4*)(kp + CC);
            float4 khv, klv, vt;
            khv.x = tf32_rna(kv.x); klv.x = tf32_rna(kv.x - khv.x);
            khv.y = tf32_rna(kv.y); klv.y = tf32_rna(kv.y - khv.y);
            khv.z = tf32_rna(kv.z); klv.z = tf32_rna(kv.z - khv.z);
            khv.w = tf32_rna(kv.w); klv.w = tf32_rna(kv.w - khv.w);
            vt.x = tf32_rna(vv.x); vt.y = tf32_rna(vv.y);
            vt.z = tf32_rna(vv.z); vt.w = tf32_rna(vv.w);
            *(float4*)&Ksh[row * KS_STRIDE + c4] = khv;
            *(float4*)&Ksl[row * KS_STRIDE + c4] = klv;
            *(float4*)&Vs [row * VS_STRIDE + c4] = vt;
        }
        __syncthreads();

        // S = Q K^T  (tf32x3)
        float sacc[8][4];
#pragma unroll
        for (int nt = 0; nt < 8; nt++)
#pragma unroll
            for (int r = 0; r < 4; r++) sacc[nt][r] = 0.0f;

#pragma unroll
        for (int nt = 0; nt < 8; nt++) {
            const int krow = nt * 8 + g;
#pragma unroll
            for (int kk = 0; kk < 8; kk++) {
                uint32_t bh0 = __float_as_uint(Ksh[krow * KS_STRIDE + kk * 8 + t]);
                uint32_t bh1 = __float_as_uint(Ksh[krow * KS_STRIDE + kk * 8 + t + 4]);
                uint32_t bl0 = __float_as_uint(Ksl[krow * KS_STRIDE + kk * 8 + t]);
                uint32_t bl1 = __float_as_uint(Ksl[krow * KS_STRIDE + kk * 8 + t + 4]);
                mma8(sacc[nt], ql[kk][0], ql[kk][1], ql[kk][2], ql[kk][3], bh0, bh1);
                mma8(sacc[nt], qh[kk][0], qh[kk][1], qh[kk][2], qh[kk][3], bl0, bl1);
                mma8(sacc[nt], qh[kk][0], qh[kk][1], qh[kk][2], qh[kk][3], bh0, bh1);
            }
        }

        // Online softmax. Thread owns rows g (regs 0,1) and g+8 (regs 2,3).
        float mx0 = -INFINITY, mx1 = -INFINITY;
#pragma unroll
        for (int nt = 0; nt < 8; nt++) {
            mx0 = fmaxf(mx0, fmaxf(sacc[nt][0], sacc[nt][1]));
            mx1 = fmaxf(mx1, fmaxf(sacc[nt][2], sacc[nt][3]));
        }
        mx0 = fmaxf(mx0, __shfl_xor_sync(0xffffffffu, mx0, 1));
        mx0 = fmaxf(mx0, __shfl_xor_sync(0xffffffffu, mx0, 2));
        mx1 = fmaxf(mx1, __shfl_xor_sync(0xffffffffu, mx1, 1));
        mx1 = fmaxf(mx1, __shfl_xor_sync(0xffffffffu, mx1, 2));

        float mn0 = fmaxf(mrow0, mx0);
        float mn1 = fmaxf(mrow1, mx1);
        float c0 = __expf(mrow0 - mn0);
        float c1 = __expf(mrow1 - mn1);
        lrow0 *= c0; lrow1 *= c1;
#pragma unroll
        for (int nt = 0; nt < 8; nt++) {
            oacc[nt][0] *= c0; oacc[nt][1] *= c0;
            oacc[nt][2] *= c1; oacc[nt][3] *= c1;
        }

        float s0 = 0.0f, s1 = 0.0f;
#pragma unroll
        for (int nt = 0; nt < 8; nt++) {
            float p00 = tf32_rna(__expf(sacc[nt][0] - mn0));
            float p01 = tf32_rna(__expf(sacc[nt][1] - mn0));
            float p10 = tf32_rna(__expf(sacc[nt][2] - mn1));
            float p11 = tf32_rna(__expf(sacc[nt][3] - mn1));
            s0 += p00 + p01;
            s1 += p10 + p11;
            int col = nt * 8 + 2 * t;
            *(float2*)&Pw[(g    ) * PS_STRIDE + col] = make_float2(p00, p01);
            *(float2*)&Pw[(g + 8) * PS_STRIDE + col] = make_float2(p10, p11);
        }
        s0 += __shfl_xor_sync(0xffffffffu, s0, 1);
        s0 += __shfl_xor_sync(0xffffffffu, s0, 2);
        s1 += __shfl_xor_sync(0xffffffffu, s1, 1);
        s1 += __shfl_xor_sync(0xffffffffu, s1, 2);
        lrow0 += s0; lrow1 += s1;
        mrow0 = mn0; mrow1 = mn1;

        __syncwarp();

        // O += P V   (plain tf32)
#pragma unroll
        for (int kk = 0; kk < 8; kk++) {
            uint32_t p0 = __float_as_uint(Pw[(g    ) * PS_STRIDE + kk * 8 + t]);
            uint32_t p1 = __float_as_uint(Pw[(g + 8) * PS_STRIDE + kk * 8 + t]);
            uint32_t p2 = __float_as_uint(Pw[(g    ) * PS_STRIDE + kk * 8 + t + 4]);
            uint32_t p3 = __float_as_uint(Pw[(g + 8) * PS_STRIDE + kk * 8 + t + 4]);
#pragma unroll
            for (int nt = 0; nt < 8; nt++) {
                uint32_t b0 = __float_as_uint(Vs[(kk * 8 + t    ) * VS_STRIDE + nt * 8 + g]);
                uint32_t b1 = __float_as_uint(Vs[(kk * 8 + t + 4) * VS_STRIDE + nt * 8 + g]);
                mma8(oacc[nt], p0, p1, p2, p3, b0, b1);
            }
        }
        __syncwarp();
    }

    // Epilogue: normalize, write [B,T,C] head-interleaved.
    const float inv0 = 1.0f / lrow0;
    const float inv1 = 1.0f / lrow1;
    float* o0 = attn + (size_t)(b * TT + q0 + g) * CC + h * 64;
    float* o1 = attn + (size_t)(b * TT + q0 + g + 8) * CC + h * 64;
#pragma unroll
    for (int nt = 0; nt < 8; nt++) {
        int col = nt * 8 + 2 * t;
        *(float2*)&o0[col] = make_float2(oacc[nt][0] * inv0, oacc[nt][1] * inv0);
        *(float2*)&o1[col] = make_float2(oacc[nt][2] * inv1, oacc[nt][3] * inv1);
    }
}

// ---------------------------------------------------------------------------
// Launch
// ---------------------------------------------------------------------------
extern "C" void kernel_launch(void* const* d_in, const int* in_sizes, int n_in,
                              void* d_out, int out_size) {
    const float* x    = (const float*)d_in[0];
    const float* Wqkv = (const float*)d_in[1];
    const float* bqkv = (const float*)d_in[2];
    const float* Wout = (const float*)d_in[3];
    const float* bout = (const float*)d_in[4];
    float* out = (float*)d_out;

    float* qkv = nullptr;
    float* attn = nullptr;
    cudaGetSymbolAddress((void**)&qkv, g_qkv);
    cudaGetSymbolAddress((void**)&attn, g_attn);

    cudaFuncSetAttribute(attn_tf32, cudaFuncAttributeMaxDynamicSharedMemorySize,
                         ATTN_SMEM_BYTES);

    // 1) QKV projection: [4096,1024] @ [1024,3072] + b
    {
        dim3 grid(C3 / 128, MTOT / 128);
        gemm_tf32x3<<<grid, 256>>>(x, Wqkv, bqkv, qkv, MTOT, C3, CC);
    }
    // 2) Flash attention (tensor core)
    {
        dim3 grid(TT / 64, HH, BB);
        attn_tf32<<<grid, 128, ATTN_SMEM_BYTES>>>(qkv, attn);
    }
    // 3) Output projection: [4096,1024] @ [1024,1024] + b
    {
        dim3 grid(CC / 128, MTOT / 128);
        gemm_tf32x3<<<grid, 256>>>(attn, Wout, bout, out, MTOT, CC, CC);
    }
}

// round 6
// speedup vs baseline: 2.5818x; 1.4775x over previous
#include <cuda_runtime.h>
#include <cuda_bf16.h>
#include <math.h>
#include <stdint.h>

#define BB 2
#define TT 2048
#define CC 1024
#define HH 16
#define C3 3072
#define MTOT (BB*TT)   // 4096

// Scratch (no allocation allowed)
__device__ float g_qkv[(size_t)MTOT * C3];
__device__ float g_attn[(size_t)MTOT * CC];

// ---------------------------------------------------------------------------
// helpers
// ---------------------------------------------------------------------------
__device__ __forceinline__ float tf32_rna(float x) {
    float r; asm("cvt.rna.tf32.f32 %0, %1;" : "=f"(r) : "f"(x)); return r;
}
// split x into bf16 hi + bf16 lo (residual)
__device__ __forceinline__ void bsplit(float x, uint16_t& h, uint16_t& l) {
    __nv_bfloat16 hb = __float2bfloat16_rn(x);
    float hf = __bfloat162float(hb);
    __nv_bfloat16 lb = __float2bfloat16_rn(x - hf);
    h = __bfloat16_as_ushort(hb);
    l = __bfloat16_as_ushort(lb);
}
// pack two bf16 (a -> low 16 bits, b -> high)
__device__ __forceinline__ uint32_t pk(uint16_t a, uint16_t b) {
    return (uint32_t)a | ((uint32_t)b << 16);
}
// split+pack a pair of floats into hi-pair and lo-pair
__device__ __forceinline__ void split_pk2(float x0, float x1, uint32_t& hi, uint32_t& lo) {
    uint16_t h0, l0, h1, l1;
    bsplit(x0, h0, l0); bsplit(x1, h1, l1);
    hi = pk(h0, h1); lo = pk(l0, l1);
}
// D += A(16x16) * B(16x8), bf16 in, fp32 accum, in place.
__device__ __forceinline__ void mma16(float* d,
                                      const uint32_t* a, uint32_t b0, uint32_t b1) {
    asm volatile(
        "mma.sync.aligned.m16n8k16.row.col.f32.bf16.bf16.f32 "
        "{%0,%1,%2,%3}, {%4,%5,%6,%7}, {%8,%9}, {%0,%1,%2,%3};\n"
        : "+f"(d[0]), "+f"(d[1]), "+f"(d[2]), "+f"(d[3])
        : "r"(a[0]), "r"(a[1]), "r"(a[2]), "r"(a[3]), "r"(b0), "r"(b1));
}
// D += A(16x8) * B(8x8), tf32 in, fp32 accum (kept for P*V)
__device__ __forceinline__ void mma8(float* d,
                                     uint32_t a0, uint32_t a1, uint32_t a2, uint32_t a3,
                                     uint32_t b0, uint32_t b1) {
    asm volatile(
        "mma.sync.aligned.m16n8k8.row.col.f32.tf32.tf32.f32 "
        "{%0,%1,%2,%3}, {%4,%5,%6,%7}, {%8,%9}, {%0,%1,%2,%3};\n"
        : "+f"(d[0]), "+f"(d[1]), "+f"(d[2]), "+f"(d[3])
        : "r"(a0), "r"(a1), "r"(a2), "r"(a3), "r"(b0), "r"(b1));
}

// ---------------------------------------------------------------------------
// GEMM (bf16x3, ~fp32 accurate): C[M,N] = A[M,K] @ W[K,N] + bias[N]
// BM=BN=128, BK=32, 256 threads (8 warps 2x4, warp tile 64x32).
// hi/lo splits precomputed at smem-load; inner loop is pure LDS + HMMA.
// Smem holds packed bf16x2 pairs along K.
// ---------------------------------------------------------------------------
__global__ void __launch_bounds__(256, 2)
gemm_bf16x3(const float* __restrict__ A, const float* __restrict__ W,
            const float* __restrict__ bias, float* __restrict__ Cout,
            int M, int N, int K) {
    __shared__ uint32_t Ah[128][20], Al[128][20];   // [row][kpair], stride 20 -> conflict-free
    __shared__ uint32_t Bh[16][136], Bl[16][136];   // [kpair][col], stride 136 -> conflict-free

    const int tid  = threadIdx.x;
    const int lane = tid & 31;
    const int wid  = tid >> 5;
    const int g = lane >> 2;        // 0..7
    const int t = lane & 3;         // 0..3
    const int wm = (wid >> 2) * 64; // 0 / 64
    const int wn = (wid & 3) * 32;  // 0..96

    const float* Ab = A + (size_t)blockIdx.y * 128 * K;
    const float* Bb = W + (size_t)blockIdx.x * 128;

    float acc[4][4][4];
#pragma unroll
    for (int i = 0; i < 4; i++)
#pragma unroll
        for (int j = 0; j < 4; j++)
#pragma unroll
            for (int r = 0; r < 4; r++) acc[i][j][r] = 0.0f;

    for (int k0 = 0; k0 < K; k0 += 32) {
        // A tile: 128x32 floats = 1024 float4, 4 per thread; split+pack on the fly
#pragma unroll
        for (int r = 0; r < 4; r++) {
            int id  = tid + r * 256;
            int row = id >> 3;            // 0..127
            int c4  = (id & 7) * 4;       // 0..28
            float4 v = *(const float4*)(Ab + (size_t)row * K + k0 + c4);
            int p = c4 >> 1;              // pair index (even)
            uint32_t h0, l0, h1, l1;
            split_pk2(v.x, v.y, h0, l0);
            split_pk2(v.z, v.w, h1, l1);
            Ah[row][p] = h0; Ah[row][p + 1] = h1;
            Al[row][p] = l0; Al[row][p + 1] = l1;
        }
        // B tile: 32x128 floats; pack pairs along K: 512 tasks, 2 per thread
#pragma unroll
        for (int r = 0; r < 2; r++) {
            int id = tid + r * 256;
            int kp = id >> 5;             // 0..15
            int n4 = (id & 31) * 4;       // 0..124
            const float* b0p = Bb + (size_t)(k0 + 2 * kp) * N + n4;
            float4 r0 = *(const float4*)b0p;
            float4 r1 = *(const float4*)(b0p + N);
            uint32_t h, l;
            uint4 hv, lv;
            uint16_t ha, la, hb, lb;
            bsplit(r0.x, ha, la); bsplit(r1.x, hb, lb); hv.x = pk(ha, hb); lv.x = pk(la, lb);
            bsplit(r0.y, ha, la); bsplit(r1.y, hb, lb); hv.y = pk(ha, hb); lv.y = pk(la, lb);
            bsplit(r0.z, ha, la); bsplit(r1.z, hb, lb); hv.z = pk(ha, hb); lv.z = pk(la, lb);
            bsplit(r0.w, ha, la); bsplit(r1.w, hb, lb); hv.w = pk(ha, hb); lv.w = pk(la, lb);
            (void)h; (void)l;
            *(uint4*)&Bh[kp][n4] = hv;
            *(uint4*)&Bl[kp][n4] = lv;
        }
        __syncthreads();

#pragma unroll
        for (int s = 0; s < 2; s++) {    // two k16 steps cover BK=32
            uint32_t ah[4][4], al[4][4];
#pragma unroll
            for (int mt = 0; mt < 4; mt++) {
                int r0 = wm + mt * 16;
                int p0 = s * 8 + t, p1 = s * 8 + t + 4;
                ah[mt][0] = Ah[r0 + g][p0];     ah[mt][1] = Ah[r0 + g + 8][p0];
                ah[mt][2] = Ah[r0 + g][p1];     ah[mt][3] = Ah[r0 + g + 8][p1];
                al[mt][0] = Al[r0 + g][p0];     al[mt][1] = Al[r0 + g + 8][p0];
                al[mt][2] = Al[r0 + g][p1];     al[mt][3] = Al[r0 + g + 8][p1];
            }
            uint32_t bh[4][2], bl[4][2];
#pragma unroll
            for (int nt = 0; nt < 4; nt++) {
                int c0 = wn + nt * 8 + g;
                bh[nt][0] = Bh[s * 8 + t][c0];     bh[nt][1] = Bh[s * 8 + t + 4][c0];
                bl[nt][0] = Bl[s * 8 + t][c0];     bl[nt][1] = Bl[s * 8 + t + 4][c0];
            }
#pragma unroll
            for (int mt = 0; mt < 4; mt++)
#pragma unroll
                for (int nt = 0; nt < 4; nt++) {
                    mma16(acc[mt][nt], al[mt], bh[nt][0], bh[nt][1]);
                    mma16(acc[mt][nt], ah[mt], bl[nt][0], bl[nt][1]);
                    mma16(acc[mt][nt], ah[mt], bh[nt][0], bh[nt][1]);
                }
        }
        __syncthreads();
    }

    // Epilogue (C layout of m16n8k16 == m16n8k8: d0,d1 row g; d2,d3 row g+8)
    float bv[4][2];
#pragma unroll
    for (int nt = 0; nt < 4; nt++) {
        int col = blockIdx.x * 128 + wn + nt * 8 + 2 * t;
        bv[nt][0] = bias[col];
        bv[nt][1] = bias[col + 1];
    }
#pragma unroll
    for (int mt = 0; mt < 4; mt++) {
        int row = blockIdx.y * 128 + wm + mt * 16 + g;
#pragma unroll
        for (int nt = 0; nt < 4; nt++) {
            int col = blockIdx.x * 128 + wn + nt * 8 + 2 * t;
            float2 v0 = make_float2(acc[mt][nt][0] + bv[nt][0],
                                    acc[mt][nt][1] + bv[nt][1]);
            float2 v1 = make_float2(acc[mt][nt][2] + bv[nt][0],
                                    acc[mt][nt][3] + bv[nt][1]);
            *(float2*)&Cout[(size_t)row * N + col]       = v0;
            *(float2*)&Cout[(size_t)(row + 8) * N + col] = v1;
        }
    }
}

// ---------------------------------------------------------------------------
// Flash attention. S=QK^T in bf16x3 (accurate), P*V in plain tf32.
// grid (T/64, H, B), 128 threads (4 warps, 16 q-rows per warp).
// K stored as packed bf16 pairs [key][kpair] (stride 36 -> frag reads conflict-free)
// ---------------------------------------------------------------------------
#define KP_STRIDE 36
#define VS_STRIDE 72
#define PS_STRIDE 68
// all offsets in 32-bit words
#define SM_KH  0
#define SM_KL  (64 * KP_STRIDE)                 // 2304
#define SM_VS  (SM_KL + 64 * KP_STRIDE)         // 4608
#define SM_PS  (SM_VS + 64 * VS_STRIDE)         // 9216
#define ATTN_SMEM_WORDS (SM_PS + 4 * 16 * PS_STRIDE)    // 13568
#define ATTN_SMEM_BYTES (ATTN_SMEM_WORDS * 4)           // 54272

__global__ void __launch_bounds__(128)
attn_bf16(const float* __restrict__ qkv, float* __restrict__ attn) {
    extern __shared__ uint32_t sm[];
    uint32_t* Kh = sm + SM_KH;              // [64][36] packed bf16-hi pairs of K
    uint32_t* Kl = sm + SM_KL;              // [64][36] packed bf16-lo pairs
    float*    Vs = (float*)(sm + SM_VS);    // [64][72] tf32(V)
    float*    Ps = (float*)(sm + SM_PS);    // [4][16][68] per-warp P

    const int tid  = threadIdx.x;
    const int lane = tid & 31;
    const int wid  = tid >> 5;
    const int g = lane >> 2;
    const int t = lane & 3;
    const int qt = blockIdx.x, h = blockIdx.y, b = blockIdx.z;

    const float* base = qkv + (size_t)b * TT * C3;
    const int q0 = qt * 64 + wid * 16;

    // Q fragments (bf16 hi/lo packed pairs), scaled by 1/8, loaded once.
    uint32_t qh[4][4], ql[4][4];
    {
        const float* qr0 = base + (size_t)(q0 + g) * C3 + h * 64;
        const float* qr1 = base + (size_t)(q0 + g + 8) * C3 + h * 64;
#pragma unroll
        for (int s = 0; s < 4; s++) {
            int p0 = s * 8 + t, p1 = s * 8 + t + 4;
            split_pk2(qr0[2*p0] * 0.125f, qr0[2*p0+1] * 0.125f, qh[s][0], ql[s][0]);
            split_pk2(qr1[2*p0] * 0.125f, qr1[2*p0+1] * 0.125f, qh[s][1], ql[s][1]);
            split_pk2(qr0[2*p1] * 0.125f, qr0[2*p1+1] * 0.125f, qh[s][2], ql[s][2]);
            split_pk2(qr1[2*p1] * 0.125f, qr1[2*p1+1] * 0.125f, qh[s][3], ql[s][3]);
        }
    }

    float mrow0 = -INFINITY, mrow1 = -INFINITY;
    float lrow0 = 0.0f, lrow1 = 0.0f;
    float oacc[8][4];
#pragma unroll
    for (int nt = 0; nt < 8; nt++)
#pragma unroll
        for (int r = 0; r < 4; r++) oacc[nt][r] = 0.0f;

    float* Pw = Ps + wid * 16 * PS_STRIDE;

    for (int kt = 0; kt < TT; kt += 64) {
        __syncthreads();
        // Load K (bf16 split, packed pairs along head-dim) and V (tf32).
#pragma unroll
        for (int r = 0; r < 8; r++) {
            int id  = tid + r * 128;
            int row = id >> 4;            // key 0..63
            int c4  = (id & 15) * 4;      // head-dim 0..60
            const float* kp = base + (size_t)(kt + row) * C3 + CC + h * 64 + c4;
            float4 kv = *(const float4*)kp;
            float4 vv = *(const float4*)(kp + CC);
            int p = c4 >> 1;
            uint32_t h0, l0, h1, l1;
            split_pk2(kv.x, kv.y, h0, l0);
            split_pk2(kv.z, kv.w, h1, l1);
            *(uint2*)&Kh[row * KP_STRIDE + p] = make_uint2(h0, h1);
            *(uint2*)&Kl[row * KP_STRIDE + p] = make_uint2(l0, l1);
            float4 vt;
            vt.x = tf32_rna(vv.x); vt.y = tf32_rna(vv.y);
            vt.z = tf32_rna(vv.z); vt.w = tf32_rna(vv.w);
            *(float4*)&Vs[row * VS_STRIDE + c4] = vt;
        }
        __syncthreads();

        // S = Q K^T  (bf16x3)
        float sacc[8][4];
#pragma unroll
        for (int nt = 0; nt < 8; nt++)
#pragma unroll
            for (int r = 0; r < 4; r++) sacc[nt][r] = 0.0f;

#pragma unroll
        for (int nt = 0; nt < 8; nt++) {
            const int kb = (nt * 8 + g) * KP_STRIDE;
#pragma unroll
            for (int s = 0; s < 4; s++) {
                uint32_t bh0 = Kh[kb + s * 8 + t];
                uint32_t bh1 = Kh[kb + s * 8 + t + 4];
                uint32_t bl0 = Kl[kb + s * 8 + t];
                uint32_t bl1 = Kl[kb + s * 8 + t + 4];
                mma16(sacc[nt], ql[s], bh0, bh1);
                mma16(sacc[nt], qh[s], bl0, bl1);
                mma16(sacc[nt], qh[s], bh0, bh1);
            }
        }

        // Online softmax. Thread owns rows g (regs 0,1) and g+8 (regs 2,3).
        float mx0 = -INFINITY, mx1 = -INFINITY;
#pragma unroll
        for (int nt = 0; nt < 8; nt++) {
            mx0 = fmaxf(mx0, fmaxf(sacc[nt][0], sacc[nt][1]));
            mx1 = fmaxf(mx1, fmaxf(sacc[nt][2], sacc[nt][3]));
        }
        mx0 = fmaxf(mx0, __shfl_xor_sync(0xffffffffu, mx0, 1));
        mx0 = fmaxf(mx0, __shfl_xor_sync(0xffffffffu, mx0, 2));
        mx1 = fmaxf(mx1, __shfl_xor_sync(0xffffffffu, mx1, 1));
        mx1 = fmaxf(mx1, __shfl_xor_sync(0xffffffffu, mx1, 2));

        float mn0 = fmaxf(mrow0, mx0);
        float mn1 = fmaxf(mrow1, mx1);
        float c0 = __expf(mrow0 - mn0);
        float c1 = __expf(mrow1 - mn1);
        lrow0 *= c0; lrow1 *= c1;
#pragma unroll
        for (int nt = 0; nt < 8; nt++) {
            oacc[nt][0] *= c0; oacc[nt][1] *= c0;
            oacc[nt][2] *= c1; oacc[nt][3] *= c1;
        }

        float s0 = 0.0f, s1 = 0.0f;
#pragma unroll
        for (int nt = 0; nt < 8; nt++) {
            float p00 = tf32_rna(__expf(sacc[nt][0] - mn0));
            float p01 = tf32_rna(__expf(sacc[nt][1] - mn0));
            float p10 = tf32_rna(__expf(sacc[nt][2] - mn1));
            float p11 = tf32_rna(__expf(sacc[nt][3] - mn1));
            s0 += p00 + p01;
            s1 += p10 + p11;
            int col = nt * 8 + 2 * t;
            *(float2*)&Pw[(g    ) * PS_STRIDE + col] = make_float2(p00, p01);
            *(float2*)&Pw[(g + 8) * PS_STRIDE + col] = make_float2(p10, p11);
        }
        s0 += __shfl_xor_sync(0xffffffffu, s0, 1);
        s0 += __shfl_xor_sync(0xffffffffu, s0, 2);
        s1 += __shfl_xor_sync(0xffffffffu, s1, 1);
        s1 += __shfl_xor_sync(0xffffffffu, s1, 2);
        lrow0 += s0; lrow1 += s1;
        mrow0 = mn0; mrow1 = mn1;

        __syncwarp();

        // O += P V   (plain tf32)
#pragma unroll
        for (int kk = 0; kk < 8; kk++) {
            uint32_t p0 = __float_as_uint(Pw[(g    ) * PS_STRIDE + kk * 8 + t]);
            uint32_t p1 = __float_as_uint(Pw[(g + 8) * PS_STRIDE + kk * 8 + t]);
            uint32_t p2 = __float_as_uint(Pw[(g    ) * PS_STRIDE + kk * 8 + t + 4]);
            uint32_t p3 = __float_as_uint(Pw[(g + 8) * PS_STRIDE + kk * 8 + t + 4]);
#pragma unroll
            for (int nt = 0; nt < 8; nt++) {
                uint32_t b0 = __float_as_uint(Vs[(kk * 8 + t    ) * VS_STRIDE + nt * 8 + g]);
                uint32_t b1 = __float_as_uint(Vs[(kk * 8 + t + 4) * VS_STRIDE + nt * 8 + g]);
                mma8(oacc[nt], p0, p1, p2, p3, b0, b1);
            }
        }
        __syncwarp();
    }

    // Epilogue: normalize, write [B,T,C] head-interleaved.
    const float inv0 = 1.0f / lrow0;
    const float inv1 = 1.0f / lrow1;
    float* o0 = attn + (size_t)(b * TT + q0 + g) * CC + h * 64;
    float* o1 = attn + (size_t)(b * TT + q0 + g + 8) * CC + h * 64;
#pragma unroll
    for (int nt = 0; nt < 8; nt++) {
        int col = nt * 8 + 2 * t;
        *(float2*)&o0[col] = make_float2(oacc[nt][0] * inv0, oacc[nt][1] * inv0);
        *(float2*)&o1[col] = make_float2(oacc[nt][2] * inv1, oacc[nt][3] * inv1);
    }
}

// ---------------------------------------------------------------------------
// Launch
// ---------------------------------------------------------------------------
extern "C" void kernel_launch(void* const* d_in, const int* in_sizes, int n_in,
                              void* d_out, int out_size) {
    const float* x    = (const float*)d_in[0];
    const float* Wqkv = (const float*)d_in[1];
    const float* bqkv = (const float*)d_in[2];
    const float* Wout = (const float*)d_in[3];
    const float* bout = (const float*)d_in[4];
    float* out = (float*)d_out;

    float* qkv = nullptr;
    float* attn = nullptr;
    cudaGetSymbolAddress((void**)&qkv, g_qkv);
    cudaGetSymbolAddress((void**)&attn, g_attn);

    cudaFuncSetAttribute(attn_bf16, cudaFuncAttributeMaxDynamicSharedMemorySize,
                         ATTN_SMEM_BYTES);

    // 1) QKV projection: [4096,1024] @ [1024,3072] + b
    {
        dim3 grid(C3 / 128, MTOT / 128);
        gemm_bf16x3<<<grid, 256>>>(x, Wqkv, bqkv, qkv, MTOT, C3, CC);
    }
    // 2) Flash attention (tensor core)
    {
        dim3 grid(TT / 64, HH, BB);
        attn_bf16<<<grid, 128, ATTN_SMEM_BYTES>>>(qkv, attn);
    }
    // 3) Output projection: [4096,1024] @ [1024,1024] + b
    {
        dim3 grid(CC / 128, MTOT / 128);
        gemm_bf16x3<<<grid, 256>>>(attn, Wout, bout, out, MTOT, CC, CC);
    }
}

// round 7
// speedup vs baseline: 3.2169x; 1.2460x over previous
#include <cuda_runtime.h>
#include <cuda_bf16.h>
#include <math.h>
#include <stdint.h>

#define BBATCH 2
#define TT 2048
#define CC 1024
#define HH 16
#define C3 3072
#define MTOT 4096
#define KP 512          // k-pairs (1024/2)

// ---------------------------------------------------------------------------
// Scratch (__device__ globals; no allocation allowed)
// ---------------------------------------------------------------------------
__device__ float    g_q [(size_t)MTOT * CC];             // fp32 Q (QKV epilogue)
__device__ uint32_t g_KH[(size_t)BBATCH*HH*TT*32];       // K bf16-hi packed [b,h,key,dp]
__device__ uint32_t g_KL[(size_t)BBATCH*HH*TT*32];       // K bf16-lo packed
__device__ float    g_V [(size_t)BBATCH*HH*TT*64];       // V tf32 [b,h,key,d]
__device__ uint32_t g_XH[(size_t)MTOT*KP];               // x split, A-plane layout
__device__ uint32_t g_XL[(size_t)MTOT*KP];
__device__ uint32_t g_WQh[(size_t)KP*C3];                // W_qkv split, B-plane layout
__device__ uint32_t g_WQl[(size_t)KP*C3];
__device__ uint32_t g_WOh[(size_t)KP*CC];                // W_out split
__device__ uint32_t g_WOl[(size_t)KP*CC];
__device__ uint32_t g_ATh[(size_t)MTOT*KP];              // attention out split (A-plane)
__device__ uint32_t g_ATl[(size_t)MTOT*KP];

// ---------------------------------------------------------------------------
// helpers
// ---------------------------------------------------------------------------
__device__ __forceinline__ float tf32_rna(float x) {
    float r; asm("cvt.rna.tf32.f32 %0, %1;" : "=f"(r) : "f"(x)); return r;
}
__device__ __forceinline__ void bsplit(float x, uint16_t& h, uint16_t& l) {
    __nv_bfloat16 hb = __float2bfloat16_rn(x);
    float hf = __bfloat162float(hb);
    __nv_bfloat16 lb = __float2bfloat16_rn(x - hf);
    h = __bfloat16_as_ushort(hb);
    l = __bfloat16_as_ushort(lb);
}
__device__ __forceinline__ uint32_t pk(uint16_t a, uint16_t b) {
    return (uint32_t)a | ((uint32_t)b << 16);
}
__device__ __forceinline__ void split_pk2(float x0, float x1, uint32_t& hi, uint32_t& lo) {
    uint16_t h0, l0, h1, l1;
    bsplit(x0, h0, l0); bsplit(x1, h1, l1);
    hi = pk(h0, h1); lo = pk(l0, l1);
}
__device__ __forceinline__ uint32_t sptr(const void* p) {
    return (uint32_t)__cvta_generic_to_shared(p);
}
__device__ __forceinline__ void ldm4(uint32_t* r, uint32_t addr) {
    asm volatile("ldmatrix.sync.aligned.m8n8.x4.shared.b16 {%0,%1,%2,%3}, [%4];"
        : "=r"(r[0]), "=r"(r[1]), "=r"(r[2]), "=r"(r[3]) : "r"(addr));
}
#define CP16(dst, src) \
    asm volatile("cp.async.cg.shared.global [%0], [%1], 16;\n" :: "r"(dst), "l"(src))
#define CP_COMMIT() asm volatile("cp.async.commit_group;\n")

__device__ __forceinline__ void mma16(float* d, const uint32_t* a,
                                      uint32_t b0, uint32_t b1) {
    asm volatile(
        "mma.sync.aligned.m16n8k16.row.col.f32.bf16.bf16.f32 "
        "{%0,%1,%2,%3}, {%4,%5,%6,%7}, {%8,%9}, {%0,%1,%2,%3};\n"
        : "+f"(d[0]), "+f"(d[1]), "+f"(d[2]), "+f"(d[3])
        : "r"(a[0]), "r"(a[1]), "r"(a[2]), "r"(a[3]), "r"(b0), "r"(b1));
}
__device__ __forceinline__ void mma8(float* d,
                                     uint32_t a0, uint32_t a1, uint32_t a2, uint32_t a3,
                                     uint32_t b0, uint32_t b1) {
    asm volatile(
        "mma.sync.aligned.m16n8k8.row.col.f32.tf32.tf32.f32 "
        "{%0,%1,%2,%3}, {%4,%5,%6,%7}, {%8,%9}, {%0,%1,%2,%3};\n"
        : "+f"(d[0]), "+f"(d[1]), "+f"(d[2]), "+f"(d[3])
        : "r"(a0), "r"(a1), "r"(a2), "r"(a3), "r"(b0), "r"(b1));
}

// ---------------------------------------------------------------------------
// Prep kernels
// ---------------------------------------------------------------------------
// A-plane split: pairs along contiguous k. one thread = one float4 (2 pairs)
__global__ void split_A_kernel(const float* __restrict__ src,
                               uint32_t* __restrict__ hi, uint32_t* __restrict__ lo,
                               int nquads) {
    int i = blockIdx.x * blockDim.x + threadIdx.x;
    if (i >= nquads) return;
    float4 v = ((const float4*)src)[i];
    uint32_t h0, l0, h1, l1;
    split_pk2(v.x, v.y, h0, l0);
    split_pk2(v.z, v.w, h1, l1);
    ((uint2*)hi)[i] = make_uint2(h0, h1);
    ((uint2*)lo)[i] = make_uint2(l0, l1);
}
// B-plane split: pairs across adjacent K rows. Wp[kp][n] = pk(W[2kp][n], W[2kp+1][n])
__global__ void split_B_kernel(const float* __restrict__ W,
                               uint32_t* __restrict__ hi, uint32_t* __restrict__ lo,
                               int N) {
    int i = blockIdx.x * blockDim.x + threadIdx.x;   // over KP * N/4
    int nq = N >> 2;
    if (i >= KP * nq) return;
    int kp = i / nq, c4 = (i - kp * nq) * 4;
    const float* p0 = W + (size_t)(2 * kp) * N + c4;
    float4 r0 = *(const float4*)p0;
    float4 r1 = *(const float4*)(p0 + N);
    uint16_t a, b, c, d;
    uint4 hv, lv;
    bsplit(r0.x, a, c); bsplit(r1.x, b, d); hv.x = pk(a, b); lv.x = pk(c, d);
    bsplit(r0.y, a, c); bsplit(r1.y, b, d); hv.y = pk(a, b); lv.y = pk(c, d);
    bsplit(r0.z, a, c); bsplit(r1.z, b, d); hv.z = pk(a, b); lv.z = pk(c, d);
    bsplit(r0.w, a, c); bsplit(r1.w, b, d); hv.w = pk(a, b); lv.w = pk(c, d);
    *(uint4*)(hi + (size_t)kp * N + c4) = hv;
    *(uint4*)(lo + (size_t)kp * N + c4) = lv;
}

// ---------------------------------------------------------------------------
// GEMM: pre-split bf16x3, cp.async double-buffer, ldmatrix A frags.
// BM=BN=128, BK=32 (16 kpairs), 256 threads (8 warps 2x4, warp tile 64x32).
// EPI 0: fp32 C + bias.  EPI 1: QKV epilogue (Q fp32 / K split / V tf32).
// ---------------------------------------------------------------------------
#define ASTG (128*20)
#define BSTG (16*136)
#define GEMM_SMEM_BYTES ((4*ASTG + 4*BSTG) * 4)   // 75776

template<int EPI>
__global__ void __launch_bounds__(256, 2)
gemm_sp(const uint32_t* __restrict__ Aph, const uint32_t* __restrict__ Apl,
        const uint32_t* __restrict__ Bph, const uint32_t* __restrict__ Bpl,
        const float* __restrict__ bias, float* __restrict__ Cout, int N) {
    extern __shared__ uint32_t smg[];
    uint32_t* sAh = smg;
    uint32_t* sAl = smg + 2 * ASTG;
    uint32_t* sBh = smg + 4 * ASTG;
    uint32_t* sBl = smg + 4 * ASTG + 2 * BSTG;

    const int tid = threadIdx.x;
    const int lane = tid & 31, wid = tid >> 5;
    const int g = lane >> 2, t = lane & 3;
    const int wm = (wid >> 2) * 64, wn = (wid & 3) * 32;
    const int bx = blockIdx.x, by = blockIdx.y;

    float acc[4][4][4];
#pragma unroll
    for (int i = 0; i < 4; i++)
#pragma unroll
        for (int j = 0; j < 4; j++)
#pragma unroll
            for (int r = 0; r < 4; r++) acc[i][j][r] = 0.0f;

    auto load_stage = [&](int st, int kp0) {
#pragma unroll
        for (int i = 0; i < 2; i++) {
            int id = tid + i * 256;
            int row = id >> 2, c = (id & 3) * 4;
            size_t go = (size_t)(by * 128 + row) * KP + kp0 + c;
            CP16(sptr(&sAh[st * ASTG + row * 20 + c]), Aph + go);
            CP16(sptr(&sAl[st * ASTG + row * 20 + c]), Apl + go);
        }
#pragma unroll
        for (int i = 0; i < 2; i++) {
            int id = tid + i * 256;
            int row = id >> 5, c = (id & 31) * 4;
            size_t go = (size_t)(kp0 + row) * N + bx * 128 + c;
            CP16(sptr(&sBh[st * BSTG + row * 136 + c]), Bph + go);
            CP16(sptr(&sBl[st * BSTG + row * 136 + c]), Bpl + go);
        }
    };

    load_stage(0, 0);
    CP_COMMIT();

    const int NK = KP / 16;   // 32
    const int arow = lane & 15;
    const int ahalf = (lane >> 4) * 4;

    for (int k = 0; k < NK; k++) {
        int st = k & 1;
        if (k + 1 < NK) {
            load_stage(st ^ 1, (k + 1) * 16);
            CP_COMMIT();
            asm volatile("cp.async.wait_group 1;\n");
        } else {
            asm volatile("cp.async.wait_group 0;\n");
        }
        __syncthreads();

#pragma unroll
        for (int s = 0; s < 2; s++) {
            const int acol = s * 8 + ahalf;
            uint32_t af[4][4], bf[4][2];
            // lo(A) x hi(B)
#pragma unroll
            for (int mt = 0; mt < 4; mt++)
                ldm4(af[mt], sptr(&sAl[st * ASTG + (wm + mt * 16 + arow) * 20 + acol]));
#pragma unroll
            for (int nt = 0; nt < 4; nt++) {
                bf[nt][0] = sBh[st * BSTG + (s * 8 + t) * 136 + wn + nt * 8 + g];
                bf[nt][1] = sBh[st * BSTG + (s * 8 + t + 4) * 136 + wn + nt * 8 + g];
            }
#pragma unroll
            for (int mt = 0; mt < 4; mt++)
#pragma unroll
                for (int nt = 0; nt < 4; nt++)
                    mma16(acc[mt][nt], af[mt], bf[nt][0], bf[nt][1]);
            // hi(A) x hi(B)   (reuse af)
#pragma unroll
            for (int mt = 0; mt < 4; mt++)
                ldm4(af[mt], sptr(&sAh[st * ASTG + (wm + mt * 16 + arow) * 20 + acol]));
#pragma unroll
            for (int mt = 0; mt < 4; mt++)
#pragma unroll
                for (int nt = 0; nt < 4; nt++)
                    mma16(acc[mt][nt], af[mt], bf[nt][0], bf[nt][1]);
            // hi(A) x lo(B)   (reuse bf)
#pragma unroll
            for (int nt = 0; nt < 4; nt++) {
                bf[nt][0] = sBl[st * BSTG + (s * 8 + t) * 136 + wn + nt * 8 + g];
                bf[nt][1] = sBl[st * BSTG + (s * 8 + t + 4) * 136 + wn + nt * 8 + g];
            }
#pragma unroll
            for (int mt = 0; mt < 4; mt++)
#pragma unroll
                for (int nt = 0; nt < 4; nt++)
                    mma16(acc[mt][nt], af[mt], bf[nt][0], bf[nt][1]);
        }
        __syncthreads();
    }

    // ---------------- epilogue ----------------
#pragma unroll
    for (int mt = 0; mt < 4; mt++) {
        int row = by * 128 + wm + mt * 16 + g;
#pragma unroll
        for (int nt = 0; nt < 4; nt++) {
            int col = bx * 128 + wn + nt * 8 + 2 * t;
            float b0v = bias[col], b1v = bias[col + 1];
            float v0 = acc[mt][nt][0] + b0v, v1 = acc[mt][nt][1] + b1v;
            float v2 = acc[mt][nt][2] + b0v, v3 = acc[mt][nt][3] + b1v;
            if (EPI == 0) {
                *(float2*)&Cout[(size_t)row * N + col]       = make_float2(v0, v1);
                *(float2*)&Cout[(size_t)(row + 8) * N + col] = make_float2(v2, v3);
            } else {
                int region = bx >> 3;   // uniform per block: 0=Q, 1=K, 2=V
                int b = row >> 11, key = row & (TT - 1);
                if (region == 0) {
                    *(float2*)&g_q[(size_t)row * CC + col]       = make_float2(v0, v1);
                    *(float2*)&g_q[(size_t)(row + 8) * CC + col] = make_float2(v2, v3);
                } else if (region == 1) {
                    int c2 = col - CC;
                    int h = c2 >> 6, dp = (c2 & 63) >> 1;
                    size_t r0 = ((size_t)(b * HH + h) * TT + key) * 32 + dp;
                    size_t r1 = r0 + 8 * 32;
                    uint32_t hh, ll;
                    split_pk2(v0, v1, hh, ll); g_KH[r0] = hh; g_KL[r0] = ll;
                    split_pk2(v2, v3, hh, ll); g_KH[r1] = hh; g_KL[r1] = ll;
                } else {
                    int c2 = col - 2 * CC;
                    int h = c2 >> 6, d = c2 & 63;
                    size_t r0 = ((size_t)(b * HH + h) * TT + key) * 64 + d;
                    size_t r1 = r0 + 8 * 64;
                    *(float2*)&g_V[r0] = make_float2(tf32_rna(v0), tf32_rna(v1));
                    *(float2*)&g_V[r1] = make_float2(tf32_rna(v2), tf32_rna(v3));
                }
            }
        }
    }
}

// ---------------------------------------------------------------------------
// Flash attention: pre-split K planes + tf32 V via cp.async double buffer,
// ldmatrix K frags, bf16x3 scores, tf32 P*V. Writes split output planes.
// grid (T/64, H, B), 128 threads.
// ---------------------------------------------------------------------------
#define KSTG (64*36)            // u32 per K stage per plane
#define VSTG (64*72)            // floats per V stage
#define PS_STRIDE 68
#define ATTN_SMEM_WORDS (4*KSTG + 2*VSTG + 4*16*PS_STRIDE)   // 22784
#define ATTN_SMEM_BYTES (ATTN_SMEM_WORDS * 4)                // 91136

__global__ void __launch_bounds__(128)
attn_sp() {
    extern __shared__ uint32_t sma[];
    uint32_t* sKh = sma;                       // [2][64][36]
    uint32_t* sKl = sma + 2 * KSTG;            // [2][64][36]
    float*    sV  = (float*)(sma + 4 * KSTG);  // [2][64][72]
    float*    sP  = (float*)(sma + 4 * KSTG + 2 * VSTG);  // [4][16][68]

    const int tid = threadIdx.x;
    const int lane = tid & 31, wid = tid >> 5;
    const int g = lane >> 2, t = lane & 3;
    const int qt = blockIdx.x, h = blockIdx.y, b = blockIdx.z;
    const int bh = b * HH + h;
    const uint32_t* KHb = g_KH + (size_t)bh * TT * 32;
    const uint32_t* KLb = g_KL + (size_t)bh * TT * 32;
    const float*    Vb  = g_V  + (size_t)bh * TT * 64;

    const int q0 = qt * 64 + wid * 16;
    const int grow = b * TT + q0;

    // Q fragments (bf16 hi/lo packed pairs), scaled 1/8, loaded once.
    uint32_t qh[4][4], ql[4][4];
    {
        const float* qr0 = g_q + (size_t)(grow + g) * CC + h * 64;
        const float* qr1 = g_q + (size_t)(grow + g + 8) * CC + h * 64;
#pragma unroll
        for (int s = 0; s < 4; s++) {
            int p0 = s * 8 + t, p1 = s * 8 + t + 4;
            split_pk2(qr0[2*p0] * 0.125f, qr0[2*p0+1] * 0.125f, qh[s][0], ql[s][0]);
            split_pk2(qr1[2*p0] * 0.125f, qr1[2*p0+1] * 0.125f, qh[s][1], ql[s][1]);
            split_pk2(qr0[2*p1] * 0.125f, qr0[2*p1+1] * 0.125f, qh[s][2], ql[s][2]);
            split_pk2(qr1[2*p1] * 0.125f, qr1[2*p1+1] * 0.125f, qh[s][3], ql[s][3]);
        }
    }

    float mrow0 = -INFINITY, mrow1 = -INFINITY;
    float lrow0 = 0.0f, lrow1 = 0.0f;
    float oacc[8][4];
#pragma unroll
    for (int nt = 0; nt < 8; nt++)
#pragma unroll
        for (int r = 0; r < 4; r++) oacc[nt][r] = 0.0f;

    float* Pw = sP + wid * 16 * PS_STRIDE;

    auto load_tile = [&](int st, int kt) {
#pragma unroll
        for (int i = 0; i < 4; i++) {
            int id = tid + i * 128;
            int row = id >> 3, c = (id & 7) * 4;
            size_t go = (size_t)(kt + row) * 32 + c;
            CP16(sptr(&sKh[st * KSTG + row * 36 + c]), KHb + go);
            CP16(sptr(&sKl[st * KSTG + row * 36 + c]), KLb + go);
        }
#pragma unroll
        for (int i = 0; i < 8; i++) {
            int id = tid + i * 128;
            int row = id >> 4, c = (id & 15) * 4;
            CP16(sptr(&sV[st * VSTG + row * 72 + c]), Vb + (size_t)(kt + row) * 64 + c);
        }
    };

    load_tile(0, 0);
    CP_COMMIT();

    const int krow = lane & 15;
    const int khalf = (lane >> 4) * 4;

    for (int kti = 0; kti < TT / 64; kti++) {
        int st = kti & 1;
        if (kti + 1 < TT / 64) {
            load_tile(st ^ 1, (kti + 1) * 64);
            CP_COMMIT();
            asm volatile("cp.async.wait_group 1;\n");
        } else {
            asm volatile("cp.async.wait_group 0;\n");
        }
        __syncthreads();

        // S = Q K^T  (bf16x3) — ldmatrix K frags, 2 nt-groups per x4
        float sacc[8][4];
#pragma unroll
        for (int nt = 0; nt < 8; nt++)
#pragma unroll
            for (int r = 0; r < 4; r++) sacc[nt][r] = 0.0f;

#pragma unroll
        for (int npp = 0; npp < 4; npp++) {
            const int kb = npp * 16;
#pragma unroll
            for (int s = 0; s < 4; s++) {
                uint32_t kf[4];
                ldm4(kf, sptr(&sKh[st * KSTG + (kb + krow) * 36 + s * 8 + khalf]));
                mma16(sacc[2*npp],     ql[s], kf[0], kf[2]);
                mma16(sacc[2*npp + 1], ql[s], kf[1], kf[3]);
                mma16(sacc[2*npp],     qh[s], kf[0], kf[2]);
                mma16(sacc[2*npp + 1], qh[s], kf[1], kf[3]);
                ldm4(kf, sptr(&sKl[st * KSTG + (kb + krow) * 36 + s * 8 + khalf]));
                mma16(sacc[2*npp],     qh[s], kf[0], kf[2]);
                mma16(sacc[2*npp + 1], qh[s], kf[1], kf[3]);
            }
        }

        // Online softmax
        float mx0 = -INFINITY, mx1 = -INFINITY;
#pragma unroll
        for (int nt = 0; nt < 8; nt++) {
            mx0 = fmaxf(mx0, fmaxf(sacc[nt][0], sacc[nt][1]));
            mx1 = fmaxf(mx1, fmaxf(sacc[nt][2], sacc[nt][3]));
        }
        mx0 = fmaxf(mx0, __shfl_xor_sync(0xffffffffu, mx0, 1));
        mx0 = fmaxf(mx0, __shfl_xor_sync(0xffffffffu, mx0, 2));
        mx1 = fmaxf(mx1, __shfl_xor_sync(0xffffffffu, mx1, 1));
        mx1 = fmaxf(mx1, __shfl_xor_sync(0xffffffffu, mx1, 2));

        float mn0 = fmaxf(mrow0, mx0);
        float mn1 = fmaxf(mrow1, mx1);
        float c0 = __expf(mrow0 - mn0);
        float c1 = __expf(mrow1 - mn1);
        lrow0 *= c0; lrow1 *= c1;
#pragma unroll
        for (int nt = 0; nt < 8; nt++) {
            oacc[nt][0] *= c0; oacc[nt][1] *= c0;
            oacc[nt][2] *= c1; oacc[nt][3] *= c1;
        }

        float s0 = 0.0f, s1 = 0.0f;
#pragma unroll
        for (int nt = 0; nt < 8; nt++) {
            float p00 = tf32_rna(__expf(sacc[nt][0] - mn0));
            float p01 = tf32_rna(__expf(sacc[nt][1] - mn0));
            float p10 = tf32_rna(__expf(sacc[nt][2] - mn1));
            float p11 = tf32_rna(__expf(sacc[nt][3] - mn1));
            s0 += p00 + p01;
            s1 += p10 + p11;
            int col = nt * 8 + 2 * t;
            *(float2*)&Pw[(g    ) * PS_STRIDE + col] = make_float2(p00, p01);
            *(float2*)&Pw[(g + 8) * PS_STRIDE + col] = make_float2(p10, p11);
        }
        s0 += __shfl_xor_sync(0xffffffffu, s0, 1);
        s0 += __shfl_xor_sync(0xffffffffu, s0, 2);
        s1 += __shfl_xor_sync(0xffffffffu, s1, 1);
        s1 += __shfl_xor_sync(0xffffffffu, s1, 2);
        lrow0 += s0; lrow1 += s1;
        mrow0 = mn0; mrow1 = mn1;

        __syncwarp();

        // O += P V   (tf32)
        const float* Vst = sV + st * VSTG;
#pragma unroll
        for (int kk = 0; kk < 8; kk++) {
            uint32_t p0 = __float_as_uint(Pw[(g    ) * PS_STRIDE + kk * 8 + t]);
            uint32_t p1 = __float_as_uint(Pw[(g + 8) * PS_STRIDE + kk * 8 + t]);
            uint32_t p2 = __float_as_uint(Pw[(g    ) * PS_STRIDE + kk * 8 + t + 4]);
            uint32_t p3 = __float_as_uint(Pw[(g + 8) * PS_STRIDE + kk * 8 + t + 4]);
#pragma unroll
            for (int nt = 0; nt < 8; nt++) {
                uint32_t b0 = __float_as_uint(Vst[(kk * 8 + t    ) * 72 + nt * 8 + g]);
                uint32_t b1 = __float_as_uint(Vst[(kk * 8 + t + 4) * 72 + nt * 8 + g]);
                mma8(oacc[nt], p0, p1, p2, p3, b0, b1);
            }
        }
        __syncthreads();
    }

    // Epilogue: normalize, write split bf16 planes (A-layout for out-proj)
    const float inv0 = 1.0f / lrow0;
    const float inv1 = 1.0f / lrow1;
    const size_t r0 = (size_t)(grow + g) * KP;
    const size_t r1 = (size_t)(grow + g + 8) * KP;
#pragma unroll
    for (int nt = 0; nt < 8; nt++) {
        int kp = h * 32 + nt * 4 + t;
        uint32_t hh, ll;
        split_pk2(oacc[nt][0] * inv0, oacc[nt][1] * inv0, hh, ll);
        g_ATh[r0 + kp] = hh; g_ATl[r0 + kp] = ll;
        split_pk2(oacc[nt][2] * inv1, oacc[nt][3] * inv1, hh, ll);
        g_ATh[r1 + kp] = hh; g_ATl[r1 + kp] = ll;
    }
}

// ---------------------------------------------------------------------------
// Launch
// ---------------------------------------------------------------------------
extern "C" void kernel_launch(void* const* d_in, const int* in_sizes, int n_in,
                              void* d_out, int out_size) {
    const float* x    = (const float*)d_in[0];
    const float* Wqkv = (const float*)d_in[1];
    const float* bqkv = (const float*)d_in[2];
    const float* Wout = (const float*)d_in[3];
    const float* bout = (const float*)d_in[4];
    float* out = (float*)d_out;

    uint32_t *XH, *XL, *WQh, *WQl, *WOh, *WOl, *ATh, *ATl;
    cudaGetSymbolAddress((void**)&XH,  g_XH);
    cudaGetSymbolAddress((void**)&XL,  g_XL);
    cudaGetSymbolAddress((void**)&WQh, g_WQh);
    cudaGetSymbolAddress((void**)&WQl, g_WQl);
    cudaGetSymbolAddress((void**)&WOh, g_WOh);
    cudaGetSymbolAddress((void**)&WOl, g_WOl);
    cudaGetSymbolAddress((void**)&ATh, g_ATh);
    cudaGetSymbolAddress((void**)&ATl, g_ATl);

    cudaFuncSetAttribute(gemm_sp<0>, cudaFuncAttributeMaxDynamicSharedMemorySize,
                         GEMM_SMEM_BYTES);
    cudaFuncSetAttribute(gemm_sp<1>, cudaFuncAttributeMaxDynamicSharedMemorySize,
                         GEMM_SMEM_BYTES);
    cudaFuncSetAttribute(attn_sp, cudaFuncAttributeMaxDynamicSharedMemorySize,
                         ATTN_SMEM_BYTES);

    // Prep: split x and weights
    {
        int nq = MTOT * CC / 4;
        split_A_kernel<<<(nq + 255) / 256, 256>>>(x, XH, XL, nq);
    }
    split_B_kernel<<<(KP * (C3 / 4) + 255) / 256, 256>>>(Wqkv, WQh, WQl, C3);
    split_B_kernel<<<(KP * (CC / 4) + 255) / 256, 256>>>(Wout, WOh, WOl, CC);

    // 1) QKV projection with fused Q/K/V-layout epilogue
    gemm_sp<1><<<dim3(C3 / 128, MTOT / 128), 256, GEMM_SMEM_BYTES>>>(
        XH, XL, WQh, WQl, bqkv, nullptr, C3);

    // 2) Flash attention (reads g_q/g_KH/g_KL/g_V; writes g_ATh/g_ATl)
    attn_sp<<<dim3(TT / 64, HH, BBATCH), 128, ATTN_SMEM_BYTES>>>();

    // 3) Output projection
    gemm_sp<0><<<dim3(CC / 128, MTOT / 128), 256, GEMM_SMEM_BYTES>>>(
        ATh, ATl, WOh, WOl, bout, out, CC);
}